// round 9
// baseline (speedup 1.0000x reference)
#include <cuda_runtime.h>
#include <cuda_fp16.h>
#include <math.h>
#include <stdint.h>

#define B_   8
#define N_   2048
#define DIN  256
#define DOUT 128
#define ROWZ 75        // rows [0,75) get attscore = 0
#define TM   128
#define TN   128
#define HST  136       // half-element stride for attn smem tiles (68 words: conflict-free)

// Scratch (device globals: allocation-free)
__device__ __half g_Whh[B_ * N_ * DOUT];   // 4 MB   Wh, fp16, row-major [n][d]
__device__ __half g_WhT[B_ * DOUT * N_];   // 4 MB   Wh^T, fp16, [d][n]
__device__ float  g_inv [B_ * N_];         // 64 KB  fp32 inverse row norms

__device__ __forceinline__ float to_tf32(float x) {
    unsigned u; asm("cvt.rna.tf32.f32 %0, %1;" : "=r"(u) : "f"(x));
    return __uint_as_float(u);
}
__device__ __forceinline__ void mma_tf32(float d[4], const unsigned a[4], const unsigned b[2]) {
    asm volatile(
        "mma.sync.aligned.m16n8k8.row.col.f32.tf32.tf32.f32 "
        "{%0,%1,%2,%3}, {%4,%5,%6,%7}, {%8,%9}, {%0,%1,%2,%3};\n"
        : "+f"(d[0]), "+f"(d[1]), "+f"(d[2]), "+f"(d[3])
        : "r"(a[0]), "r"(a[1]), "r"(a[2]), "r"(a[3]), "r"(b[0]), "r"(b[1]));
}
__device__ __forceinline__ void mma_f16(float d[4], const unsigned a[4], const unsigned b[2]) {
    asm volatile(
        "mma.sync.aligned.m16n8k16.row.col.f32.f16.f16.f32 "
        "{%0,%1,%2,%3}, {%4,%5,%6,%7}, {%8,%9}, {%0,%1,%2,%3};\n"
        : "+f"(d[0]), "+f"(d[1]), "+f"(d[2]), "+f"(d[3])
        : "r"(a[0]), "r"(a[1]), "r"(a[2]), "r"(a[3]), "r"(b[0]), "r"(b[1]));
}

// ---------------------------------------------------------------------------
// Phase 1: Wh = h @ W on tf32 MMA, fused row-norm. Outputs fp16 Wh + Wh^T + inv.
// ---------------------------------------------------------------------------
__global__ __launch_bounds__(256) void gemmW(const float* __restrict__ h,
                                             const float* __restrict__ W) {
    __shared__ float hs[128 * 36];
    __shared__ float Ws[32 * 132];
    __shared__ float sq[128];

    const int r0  = blockIdx.x * 128;
    const int tid = threadIdx.x;
    const int w   = tid >> 5, lane = tid & 31;
    const int mqw = (w & 3) * 32, dw = (w >> 2) * 64;
    const int qr  = lane >> 2,  qc = lane & 3;

    if (tid < 128) sq[tid] = 0.0f;

    float acc[2][8][4];
#pragma unroll
    for (int mb = 0; mb < 2; mb++)
#pragma unroll
        for (int nb = 0; nb < 8; nb++)
#pragma unroll
            for (int c = 0; c < 4; c++) acc[mb][nb][c] = 0.0f;

    for (int kc = 0; kc < 8; kc++) {
        __syncthreads();
#pragma unroll
        for (int i = tid; i < 128 * 8; i += 256) {
            int r = i >> 3, g = (i & 7) * 4;
            float4 v = *(const float4*)&h[(size_t)(r0 + r) * DIN + kc * 32 + g];
            v.x = to_tf32(v.x); v.y = to_tf32(v.y); v.z = to_tf32(v.z); v.w = to_tf32(v.w);
            *(float4*)&hs[r * 36 + g] = v;
        }
#pragma unroll
        for (int i = tid; i < 32 * 32; i += 256) {
            int r = i >> 5, g = (i & 31) * 4;
            float4 v = *(const float4*)&W[(size_t)(kc * 32 + r) * DOUT + g];
            v.x = to_tf32(v.x); v.y = to_tf32(v.y); v.z = to_tf32(v.z); v.w = to_tf32(v.w);
            *(float4*)&Ws[r * 132 + g] = v;
        }
        __syncthreads();

#pragma unroll
        for (int k0 = 0; k0 < 32; k0 += 8) {
            unsigned a[2][4];
#pragma unroll
            for (int mb = 0; mb < 2; mb++) {
                int base = (mqw + 16 * mb + qr) * 36 + k0 + qc;
                a[mb][0] = *(const unsigned*)&hs[base];
                a[mb][1] = *(const unsigned*)&hs[base + 8 * 36];
                a[mb][2] = *(const unsigned*)&hs[base + 4];
                a[mb][3] = *(const unsigned*)&hs[base + 8 * 36 + 4];
            }
#pragma unroll
            for (int nb = 0; nb < 8; nb++) {
                unsigned bb[2];
                bb[0] = *(const unsigned*)&Ws[(k0 + qc) * 132 + dw + 8 * nb + qr];
                bb[1] = *(const unsigned*)&Ws[(k0 + 4 + qc) * 132 + dw + 8 * nb + qr];
                mma_tf32(acc[0][nb], a[0], bb);
                mma_tf32(acc[1][nb], a[1], bb);
            }
        }
    }

    // row square-sums (fp32)
#pragma unroll
    for (int mb = 0; mb < 2; mb++) {
        float s0 = 0.0f, s1 = 0.0f;
#pragma unroll
        for (int nb = 0; nb < 8; nb++) {
            s0 += acc[mb][nb][0] * acc[mb][nb][0] + acc[mb][nb][1] * acc[mb][nb][1];
            s1 += acc[mb][nb][2] * acc[mb][nb][2] + acc[mb][nb][3] * acc[mb][nb][3];
        }
        s0 += __shfl_xor_sync(0xffffffffu, s0, 1); s0 += __shfl_xor_sync(0xffffffffu, s0, 2);
        s1 += __shfl_xor_sync(0xffffffffu, s1, 1); s1 += __shfl_xor_sync(0xffffffffu, s1, 2);
        if (qc == 0) {
            atomicAdd(&sq[mqw + 16 * mb + qr],     s0);
            atomicAdd(&sq[mqw + 16 * mb + 8 + qr], s1);
        }
    }
    __syncthreads();

    const int bb_  = r0 >> 11;               // batch
    const int rl0  = r0 & 2047;              // row within batch
    __half* WT = g_WhT + (size_t)bb_ * DOUT * N_;

#pragma unroll
    for (int mb = 0; mb < 2; mb++)
#pragma unroll
        for (int nb = 0; nb < 8; nb++) {
            int col = dw + 8 * nb + 2 * qc;
            int ra  = mqw + 16 * mb + qr, rb = ra + 8;
            __half2 ha = __floats2half2_rn(acc[mb][nb][0], acc[mb][nb][1]);
            __half2 hb = __floats2half2_rn(acc[mb][nb][2], acc[mb][nb][3]);
            *(__half2*)&g_Whh[(size_t)(r0 + ra) * DOUT + col] = ha;
            *(__half2*)&g_Whh[(size_t)(r0 + rb) * DOUT + col] = hb;
            WT[(size_t)col       * N_ + rl0 + ra] = __low2half(ha);
            WT[(size_t)(col + 1) * N_ + rl0 + ra] = __high2half(ha);
            WT[(size_t)col       * N_ + rl0 + rb] = __low2half(hb);
            WT[(size_t)(col + 1) * N_ + rl0 + rb] = __high2half(hb);
        }
    if (tid < 128) g_inv[r0 + tid] = 1.0f / fmaxf(sqrtf(sq[tid]), 1e-12f);
}

// ---------------------------------------------------------------------------
// Phase 2: fused masked-softmax attention, fp16 MMA (m16n8k16), fp32 accum.
// 512 threads, TM=TN=128. Warps: 4 q-bands(32q) x 4 splits (32k S / 32d PV).
// ---------------------------------------------------------------------------
__global__ __launch_bounds__(512, 1) void attn(const int* __restrict__ adj,
                                               float* __restrict__ out) {
    extern __shared__ __align__(16) char smraw[];
    __half* Qh   = (__half*)smraw;            // [128][136]
    __half* Kh   = Qh + TM * HST;             // [128][136]
    __half* Vt   = Kh + TN * HST;             // [128][136]  (d-major)
    __half* Ps   = Vt + TN * HST;             // [128][136]
    float*  invk = (float*)(Ps + TM * HST);   // [128]
    float*  dn   = invk + 128;                // [128]

    const int b    = blockIdx.y;
    const int q0   = blockIdx.x * TM;
    const int tid  = threadIdx.x;
    const int w    = tid >> 5, lane = tid & 31;
    const int band = w & 3, split = w >> 2;
    const int mqw  = band * 32;
    const int nkw  = split * 32;
    const int dw   = split * 32;
    const int qr   = lane >> 2, qc = lane & 3;

    const __half* WhB  = g_Whh + (size_t)b * N_ * DOUT;
    const __half* WtB  = g_WhT + (size_t)b * DOUT * N_;
    const float*  invB = g_inv + (size_t)b * N_;
    const int*    adjB = adj   + (size_t)b * N_ * N_;

    // Q tile (coalesced: 16 lanes cover one 256B row)
#pragma unroll
    for (int i = tid; i < TM * 16; i += 512) {
        int r = i >> 4, ho = (i & 15) * 8;
        *(uint4*)&Qh[r * HST + ho] = *(const uint4*)&WhB[(size_t)(q0 + r) * DOUT + ho];
    }
    if (tid < 128) dn[tid] = 0.0f;

    float ivq[4]; bool zq[4];
#pragma unroll
    for (int rr = 0; rr < 4; rr++) {
        int row = mqw + 16 * (rr >> 1) + 8 * (rr & 1) + qr;
        ivq[rr] = __ldg(&invB[q0 + row]);
        zq[rr]  = (q0 + row) < ROWZ;
    }
    const int* ap[4];
#pragma unroll
    for (int rr = 0; rr < 4; rr++)
        ap[rr] = adjB + (size_t)(q0 + mqw + 16 * (rr >> 1) + 8 * (rr & 1) + qr) * N_ + nkw + 2 * qc;

    float oacc[2][4][4];
#pragma unroll
    for (int mb = 0; mb < 2; mb++)
#pragma unroll
        for (int nb = 0; nb < 4; nb++)
#pragma unroll
            for (int c = 0; c < 4; c++) oacc[mb][nb][c] = 0.0f;
    float rsum[4] = {0.f, 0.f, 0.f, 0.f};

    for (int m0 = 0; m0 < N_; m0 += TN) {
        __syncthreads();   // prev tile's MMA reads of Kh/Vt/Ps complete
        // K (row-major) + Vt (d-major) tiles, invk
#pragma unroll
        for (int i = tid; i < TN * 16; i += 512) {
            int r = i >> 4, ho = (i & 15) * 8;
            *(uint4*)&Kh[r * HST + ho] = *(const uint4*)&WhB[(size_t)(m0 + r) * DOUT + ho];
            *(uint4*)&Vt[r * HST + ho] = *(const uint4*)&WtB[(size_t)r * N_ + m0 + ho];
        }
        if (tid < 128) invk[tid] = invB[m0 + tid];

        unsigned msk = 0;
#pragma unroll
        for (int rr = 0; rr < 4; rr++) {
#pragma unroll
            for (int nb = 0; nb < 4; nb++) {
                int2 v = *(const int2*)(ap[rr] + 8 * nb);
                msk |= (unsigned)(v.x > 0) << (rr * 8 + nb * 2);
                msk |= (unsigned)(v.y > 0) << (rr * 8 + nb * 2 + 1);
            }
            ap[rr] += TN;
        }
        __syncthreads();   // tiles visible

        // ---- S = Q.K^T  (warp: 32q x 32k, fp16 k=16 steps) ----
        float sacc[2][4][4];
#pragma unroll
        for (int mb = 0; mb < 2; mb++)
#pragma unroll
            for (int nb = 0; nb < 4; nb++)
#pragma unroll
                for (int c = 0; c < 4; c++) sacc[mb][nb][c] = 0.0f;

#pragma unroll
        for (int k0 = 0; k0 < DOUT; k0 += 16) {
            unsigned a[2][4];
#pragma unroll
            for (int mb = 0; mb < 2; mb++) {
                int base = (mqw + 16 * mb + qr) * HST + k0 + 2 * qc;
                a[mb][0] = *(const unsigned*)&Qh[base];
                a[mb][1] = *(const unsigned*)&Qh[base + 8 * HST];
                a[mb][2] = *(const unsigned*)&Qh[base + 8];
                a[mb][3] = *(const unsigned*)&Qh[base + 8 * HST + 8];
            }
#pragma unroll
            for (int nb = 0; nb < 4; nb++) {
                int bbase = (nkw + 8 * nb + qr) * HST + k0 + 2 * qc;
                unsigned bb[2];
                bb[0] = *(const unsigned*)&Kh[bbase];
                bb[1] = *(const unsigned*)&Kh[bbase + 8];
                mma_f16(sacc[0][nb], a[0], bb);
                mma_f16(sacc[1][nb], a[1], bb);
            }
        }

        // ---- scale + mask + exp -> P (fp16) ----
#pragma unroll
        for (int mb = 0; mb < 2; mb++) {
#pragma unroll
            for (int nb = 0; nb < 4; nb++) {
                int cb = nkw + 8 * nb + 2 * qc;
                float k0i = invk[cb], k1i = invk[cb + 1];
                unsigned ml = msk >> ((mb * 2)     * 8 + nb * 2);
                unsigned mh = msk >> ((mb * 2 + 1) * 8 + nb * 2);
                float p0 = (ml & 1u) ? __expf(zq[mb*2]   ? 0.f : sacc[mb][nb][0] * ivq[mb*2]   * k0i) : 0.f;
                float p1 = (ml & 2u) ? __expf(zq[mb*2]   ? 0.f : sacc[mb][nb][1] * ivq[mb*2]   * k1i) : 0.f;
                float p2 = (mh & 1u) ? __expf(zq[mb*2+1] ? 0.f : sacc[mb][nb][2] * ivq[mb*2+1] * k0i) : 0.f;
                float p3 = (mh & 2u) ? __expf(zq[mb*2+1] ? 0.f : sacc[mb][nb][3] * ivq[mb*2+1] * k1i) : 0.f;
                __half2 ha = __floats2half2_rn(p0, p1);
                __half2 hb = __floats2half2_rn(p2, p3);
                float2 fa = __half22float2(ha), fb = __half22float2(hb);
                rsum[mb * 2]     += fa.x + fa.y;
                rsum[mb * 2 + 1] += fb.x + fb.y;
                *(__half2*)&Ps[(mqw + 16 * mb + qr) * HST + cb]     = ha;
                *(__half2*)&Ps[(mqw + 16 * mb + 8 + qr) * HST + cb] = hb;
            }
        }
        __syncthreads();   // P complete (cross-split reads next)

        // ---- O += P.V  (warp: 32q x 32d, B = Vt[d][key]) ----
#pragma unroll
        for (int k0 = 0; k0 < TN; k0 += 16) {
            unsigned a[2][4];
#pragma unroll
            for (int mb = 0; mb < 2; mb++) {
                int base = (mqw + 16 * mb + qr) * HST + k0 + 2 * qc;
                a[mb][0] = *(const unsigned*)&Ps[base];
                a[mb][1] = *(const unsigned*)&Ps[base + 8 * HST];
                a[mb][2] = *(const unsigned*)&Ps[base + 8];
                a[mb][3] = *(const unsigned*)&Ps[base + 8 * HST + 8];
            }
#pragma unroll
            for (int nb = 0; nb < 4; nb++) {
                int bbase = (dw + 8 * nb + qr) * HST + k0 + 2 * qc;
                unsigned bb[2];
                bb[0] = *(const unsigned*)&Vt[bbase];
                bb[1] = *(const unsigned*)&Vt[bbase + 8];
                mma_f16(oacc[0][nb], a[0], bb);
                mma_f16(oacc[1][nb], a[1], bb);
            }
        }
    }

    // denominators
#pragma unroll
    for (int rr = 0; rr < 4; rr++) {
        float v = rsum[rr];
        v += __shfl_xor_sync(0xffffffffu, v, 1);
        v += __shfl_xor_sync(0xffffffffu, v, 2);
        if (qc == 0) atomicAdd(&dn[mqw + 16 * (rr >> 1) + 8 * (rr & 1) + qr], v);
    }
    __syncthreads();

    // epilogue: divide, ELU, store
#pragma unroll
    for (int mb = 0; mb < 2; mb++) {
        float i0 = 1.0f / fmaxf(dn[mqw + 16 * mb + qr],     1e-30f);
        float i1 = 1.0f / fmaxf(dn[mqw + 16 * mb + 8 + qr], 1e-30f);
        int r0 = q0 + mqw + 16 * mb + qr;
#pragma unroll
        for (int nb = 0; nb < 4; nb++) {
            int col = dw + 8 * nb + 2 * qc;
            float v0 = oacc[mb][nb][0] * i0, v1 = oacc[mb][nb][1] * i0;
            float v2 = oacc[mb][nb][2] * i1, v3 = oacc[mb][nb][3] * i1;
            v0 = (v0 > 0.f) ? v0 : expm1f(v0);
            v1 = (v1 > 0.f) ? v1 : expm1f(v1);
            v2 = (v2 > 0.f) ? v2 : expm1f(v2);
            v3 = (v3 > 0.f) ? v3 : expm1f(v3);
            *(float2*)&out[((size_t)b * N_ + r0)     * DOUT + col] = make_float2(v0, v1);
            *(float2*)&out[((size_t)b * N_ + r0 + 8) * DOUT + col] = make_float2(v2, v3);
        }
    }
}

// ---------------------------------------------------------------------------
// Launch
// ---------------------------------------------------------------------------
extern "C" void kernel_launch(void* const* d_in, const int* in_sizes, int n_in,
                              void* d_out, int out_size) {
    const float* h       = (const float*)d_in[0];   // [8,2048,256] f32
    // d_in[1] = adj (unused by the reference math)
    const int*   adj_eye = (const int*)d_in[2];     // [8,2048,2048] i32
    const float* W       = (const float*)d_in[3];   // [256,128] f32
    float* out = (float*)d_out;                     // [8,2048,128] f32

    const int smem_bytes = 4 * TM * HST * 2 + 2 * 128 * 4 + 256;   // 140,544 B
    cudaFuncSetAttribute(attn, cudaFuncAttributeMaxDynamicSharedMemorySize, smem_bytes);

    gemmW<<<(B_ * N_) / 128, 256>>>(h, W);
    attn<<<dim3(N_ / TM, B_), 512, smem_bytes>>>(adj_eye, out);
}

// round 10
// speedup vs baseline: 1.3132x; 1.3132x over previous
#include <cuda_runtime.h>
#include <cuda_fp16.h>
#include <math.h>
#include <stdint.h>

#define B_   8
#define N_   2048
#define DIN  256
#define DOUT 128
#define ROWZ 75        // rows [0,75) get attscore = 0
#define TM   64        // queries per block
#define TN   128       // keys per tile
#define HST  136       // half-element stride (68 words: conflict-free fragments)

// Scratch (device globals: allocation-free)
__device__ __half g_Whh[B_ * N_ * DOUT];   // 4 MB   Wh, fp16, row-major [n][d]
__device__ __half g_WhT[B_ * DOUT * N_];   // 4 MB   Wh^T, fp16, [d][n]
__device__ float  g_inv [B_ * N_];         // 64 KB  fp32 inverse row norms

__device__ __forceinline__ float to_tf32(float x) {
    unsigned u; asm("cvt.rna.tf32.f32 %0, %1;" : "=r"(u) : "f"(x));
    return __uint_as_float(u);
}
__device__ __forceinline__ void mma_tf32(float d[4], const unsigned a[4], const unsigned b[2]) {
    asm volatile(
        "mma.sync.aligned.m16n8k8.row.col.f32.tf32.tf32.f32 "
        "{%0,%1,%2,%3}, {%4,%5,%6,%7}, {%8,%9}, {%0,%1,%2,%3};\n"
        : "+f"(d[0]), "+f"(d[1]), "+f"(d[2]), "+f"(d[3])
        : "r"(a[0]), "r"(a[1]), "r"(a[2]), "r"(a[3]), "r"(b[0]), "r"(b[1]));
}
__device__ __forceinline__ void mma_f16(float d[4], const unsigned a[4], const unsigned b[2]) {
    asm volatile(
        "mma.sync.aligned.m16n8k16.row.col.f32.f16.f16.f32 "
        "{%0,%1,%2,%3}, {%4,%5,%6,%7}, {%8,%9}, {%0,%1,%2,%3};\n"
        : "+f"(d[0]), "+f"(d[1]), "+f"(d[2]), "+f"(d[3])
        : "r"(a[0]), "r"(a[1]), "r"(a[2]), "r"(a[3]), "r"(b[0]), "r"(b[1]));
}

// ---------------------------------------------------------------------------
// Phase 1: Wh = h @ W on tf32 MMA, fused row-norm. Outputs fp16 Wh + Wh^T + inv.
// (unchanged from R9 — passing)
// ---------------------------------------------------------------------------
__global__ __launch_bounds__(256) void gemmW(const float* __restrict__ h,
                                             const float* __restrict__ W) {
    __shared__ float hs[128 * 36];
    __shared__ float Ws[32 * 132];
    __shared__ float sq[128];

    const int r0  = blockIdx.x * 128;
    const int tid = threadIdx.x;
    const int w   = tid >> 5, lane = tid & 31;
    const int mqw = (w & 3) * 32, dw = (w >> 2) * 64;
    const int qr  = lane >> 2,  qc = lane & 3;

    if (tid < 128) sq[tid] = 0.0f;

    float acc[2][8][4];
#pragma unroll
    for (int mb = 0; mb < 2; mb++)
#pragma unroll
        for (int nb = 0; nb < 8; nb++)
#pragma unroll
            for (int c = 0; c < 4; c++) acc[mb][nb][c] = 0.0f;

    for (int kc = 0; kc < 8; kc++) {
        __syncthreads();
#pragma unroll
        for (int i = tid; i < 128 * 8; i += 256) {
            int r = i >> 3, g = (i & 7) * 4;
            float4 v = *(const float4*)&h[(size_t)(r0 + r) * DIN + kc * 32 + g];
            v.x = to_tf32(v.x); v.y = to_tf32(v.y); v.z = to_tf32(v.z); v.w = to_tf32(v.w);
            *(float4*)&hs[r * 36 + g] = v;
        }
#pragma unroll
        for (int i = tid; i < 32 * 32; i += 256) {
            int r = i >> 5, g = (i & 31) * 4;
            float4 v = *(const float4*)&W[(size_t)(kc * 32 + r) * DOUT + g];
            v.x = to_tf32(v.x); v.y = to_tf32(v.y); v.z = to_tf32(v.z); v.w = to_tf32(v.w);
            *(float4*)&Ws[r * 132 + g] = v;
        }
        __syncthreads();

#pragma unroll
        for (int k0 = 0; k0 < 32; k0 += 8) {
            unsigned a[2][4];
#pragma unroll
            for (int mb = 0; mb < 2; mb++) {
                int base = (mqw + 16 * mb + qr) * 36 + k0 + qc;
                a[mb][0] = *(const unsigned*)&hs[base];
                a[mb][1] = *(const unsigned*)&hs[base + 8 * 36];
                a[mb][2] = *(const unsigned*)&hs[base + 4];
                a[mb][3] = *(const unsigned*)&hs[base + 8 * 36 + 4];
            }
#pragma unroll
            for (int nb = 0; nb < 8; nb++) {
                unsigned bb[2];
                bb[0] = *(const unsigned*)&Ws[(k0 + qc) * 132 + dw + 8 * nb + qr];
                bb[1] = *(const unsigned*)&Ws[(k0 + 4 + qc) * 132 + dw + 8 * nb + qr];
                mma_tf32(acc[0][nb], a[0], bb);
                mma_tf32(acc[1][nb], a[1], bb);
            }
        }
    }

#pragma unroll
    for (int mb = 0; mb < 2; mb++) {
        float s0 = 0.0f, s1 = 0.0f;
#pragma unroll
        for (int nb = 0; nb < 8; nb++) {
            s0 += acc[mb][nb][0] * acc[mb][nb][0] + acc[mb][nb][1] * acc[mb][nb][1];
            s1 += acc[mb][nb][2] * acc[mb][nb][2] + acc[mb][nb][3] * acc[mb][nb][3];
        }
        s0 += __shfl_xor_sync(0xffffffffu, s0, 1); s0 += __shfl_xor_sync(0xffffffffu, s0, 2);
        s1 += __shfl_xor_sync(0xffffffffu, s1, 1); s1 += __shfl_xor_sync(0xffffffffu, s1, 2);
        if (qc == 0) {
            atomicAdd(&sq[mqw + 16 * mb + qr],     s0);
            atomicAdd(&sq[mqw + 16 * mb + 8 + qr], s1);
        }
    }
    __syncthreads();

    const int bb_  = r0 >> 11;
    const int rl0  = r0 & 2047;
    __half* WT = g_WhT + (size_t)bb_ * DOUT * N_;

#pragma unroll
    for (int mb = 0; mb < 2; mb++)
#pragma unroll
        for (int nb = 0; nb < 8; nb++) {
            int col = dw + 8 * nb + 2 * qc;
            int ra  = mqw + 16 * mb + qr, rb = ra + 8;
            __half2 ha = __floats2half2_rn(acc[mb][nb][0], acc[mb][nb][1]);
            __half2 hb = __floats2half2_rn(acc[mb][nb][2], acc[mb][nb][3]);
            *(__half2*)&g_Whh[(size_t)(r0 + ra) * DOUT + col] = ha;
            *(__half2*)&g_Whh[(size_t)(r0 + rb) * DOUT + col] = hb;
            WT[(size_t)col       * N_ + rl0 + ra] = __low2half(ha);
            WT[(size_t)(col + 1) * N_ + rl0 + ra] = __high2half(ha);
            WT[(size_t)col       * N_ + rl0 + rb] = __low2half(hb);
            WT[(size_t)(col + 1) * N_ + rl0 + rb] = __high2half(hb);
        }
    if (tid < 128) g_inv[r0 + tid] = 1.0f / fmaxf(sqrtf(sq[tid]), 1e-12f);
}

// ---------------------------------------------------------------------------
// Phase 2: fused masked-softmax attention, fp16 MMA, 2 blocks/SM.
// 256 threads, TM=64, TN=128. Warps: 4 bands(16q) x 2 splits (64k S / 64d PV).
// ---------------------------------------------------------------------------
__global__ __launch_bounds__(256, 2) void attn(const int* __restrict__ adj,
                                               float* __restrict__ out) {
    extern __shared__ __align__(16) char smraw[];
    __half* Qh   = (__half*)smraw;            // [64][136]
    __half* Kh   = Qh + TM * HST;             // [128][136]
    __half* Vt   = Kh + TN * HST;             // [128][136] (d-major)
    __half* Ps   = Vt + TN * HST;             // [64][136]
    float*  invk = (float*)(Ps + TM * HST);   // [128]
    float*  dn   = invk + 128;                // [64]

    const int b     = blockIdx.y;
    const int q0    = blockIdx.x * TM;
    const int tid   = threadIdx.x;
    const int w     = tid >> 5, lane = tid & 31;
    const int band  = w & 3, split = w >> 2;   // 4 bands x 2 splits
    const int mqw   = band * 16;
    const int nkw   = split * 64;              // S key offset
    const int dw    = split * 64;              // PV d offset
    const int qr    = lane >> 2, qc = lane & 3;

    const __half* WhB  = g_Whh + (size_t)b * N_ * DOUT;
    const __half* WtB  = g_WhT + (size_t)b * DOUT * N_;
    const float*  invB = g_inv + (size_t)b * N_;
    const int*    adjB = adj   + (size_t)b * N_ * N_;

    // Q tile
#pragma unroll
    for (int i = tid; i < TM * 16; i += 256) {
        int r = i >> 4, ho = (i & 15) * 8;
        *(uint4*)&Qh[r * HST + ho] = *(const uint4*)&WhB[(size_t)(q0 + r) * DOUT + ho];
    }
    if (tid < TM) dn[tid] = 0.0f;

    float ivq[2]; bool zq[2];
#pragma unroll
    for (int rp = 0; rp < 2; rp++) {
        int row = mqw + 8 * rp + qr;
        ivq[rp] = __ldg(&invB[q0 + row]);
        zq[rp]  = (q0 + row) < ROWZ;
    }
    const int* ap[2];
#pragma unroll
    for (int rp = 0; rp < 2; rp++)
        ap[rp] = adjB + (size_t)(q0 + mqw + 8 * rp + qr) * N_ + nkw + 2 * qc;

    float oacc[8][4];
#pragma unroll
    for (int nb = 0; nb < 8; nb++)
#pragma unroll
        for (int c = 0; c < 4; c++) oacc[nb][c] = 0.0f;
    float rsum[2] = {0.f, 0.f};

    for (int m0 = 0; m0 < N_; m0 += TN) {
        __syncthreads();   // prev tile's MMA reads complete
        // K (row-major) + Vt (d-major) tiles, invk
#pragma unroll
        for (int i = tid; i < TN * 16; i += 256) {
            int r = i >> 4, ho = (i & 15) * 8;
            *(uint4*)&Kh[r * HST + ho] = *(const uint4*)&WhB[(size_t)(m0 + r) * DOUT + ho];
            *(uint4*)&Vt[r * HST + ho] = *(const uint4*)&WtB[(size_t)r * N_ + m0 + ho];
        }
        if (tid < 128) invk[tid] = invB[m0 + tid];

        // adjacency masks: bit = rp*16 + nb*2 + c
        unsigned msk = 0;
#pragma unroll
        for (int rp = 0; rp < 2; rp++) {
#pragma unroll
            for (int nb = 0; nb < 8; nb++) {
                int2 v = *(const int2*)(ap[rp] + 8 * nb);
                msk |= (unsigned)(v.x > 0) << (rp * 16 + nb * 2);
                msk |= (unsigned)(v.y > 0) << (rp * 16 + nb * 2 + 1);
            }
            ap[rp] += TN;
        }
        __syncthreads();   // tiles visible

        // ---- S = Q.K^T  (warp: 16q x 64k) ----
        float sacc[8][4];
#pragma unroll
        for (int nb = 0; nb < 8; nb++)
#pragma unroll
            for (int c = 0; c < 4; c++) sacc[nb][c] = 0.0f;

#pragma unroll
        for (int k0 = 0; k0 < DOUT; k0 += 16) {
            unsigned a[4];
            int base = (mqw + qr) * HST + k0 + 2 * qc;
            a[0] = *(const unsigned*)&Qh[base];
            a[1] = *(const unsigned*)&Qh[base + 8 * HST];
            a[2] = *(const unsigned*)&Qh[base + 8];
            a[3] = *(const unsigned*)&Qh[base + 8 * HST + 8];
#pragma unroll
            for (int nb = 0; nb < 8; nb++) {
                int bbase = (nkw + 8 * nb + qr) * HST + k0 + 2 * qc;
                unsigned bb[2];
                bb[0] = *(const unsigned*)&Kh[bbase];
                bb[1] = *(const unsigned*)&Kh[bbase + 8];
                mma_f16(sacc[nb], a, bb);
            }
        }

        // ---- scale + mask + exp -> P (fp16) ----
#pragma unroll
        for (int nb = 0; nb < 8; nb++) {
            int cb = nkw + 8 * nb + 2 * qc;
            float k0i = invk[cb], k1i = invk[cb + 1];
            unsigned ml = msk >> (nb * 2);
            unsigned mh = msk >> (16 + nb * 2);
            float p0 = (ml & 1u) ? __expf(zq[0] ? 0.f : sacc[nb][0] * ivq[0] * k0i) : 0.f;
            float p1 = (ml & 2u) ? __expf(zq[0] ? 0.f : sacc[nb][1] * ivq[0] * k1i) : 0.f;
            float p2 = (mh & 1u) ? __expf(zq[1] ? 0.f : sacc[nb][2] * ivq[1] * k0i) : 0.f;
            float p3 = (mh & 2u) ? __expf(zq[1] ? 0.f : sacc[nb][3] * ivq[1] * k1i) : 0.f;
            __half2 ha = __floats2half2_rn(p0, p1);
            __half2 hb = __floats2half2_rn(p2, p3);
            float2 fa = __half22float2(ha), fb = __half22float2(hb);
            rsum[0] += fa.x + fa.y;
            rsum[1] += fb.x + fb.y;
            *(__half2*)&Ps[(mqw + qr) * HST + cb]     = ha;
            *(__half2*)&Ps[(mqw + 8 + qr) * HST + cb] = hb;
        }
        __syncthreads();   // P complete (cross-split reads next)

        // ---- O += P.V  (warp: 16q x 64d, B = Vt[d][key]) ----
#pragma unroll
        for (int k0 = 0; k0 < TN; k0 += 16) {
            unsigned a[4];
            int base = (mqw + qr) * HST + k0 + 2 * qc;
            a[0] = *(const unsigned*)&Ps[base];
            a[1] = *(const unsigned*)&Ps[base + 8 * HST];
            a[2] = *(const unsigned*)&Ps[base + 8];
            a[3] = *(const unsigned*)&Ps[base + 8 * HST + 8];
#pragma unroll
            for (int nb = 0; nb < 8; nb++) {
                int bbase = (dw + 8 * nb + qr) * HST + k0 + 2 * qc;
                unsigned bb[2];
                bb[0] = *(const unsigned*)&Vt[bbase];
                bb[1] = *(const unsigned*)&Vt[bbase + 8];
                mma_f16(oacc[nb], a, bb);
            }
        }
    }

    // denominators (two splits per row add their halves)
#pragma unroll
    for (int rp = 0; rp < 2; rp++) {
        float v = rsum[rp];
        v += __shfl_xor_sync(0xffffffffu, v, 1);
        v += __shfl_xor_sync(0xffffffffu, v, 2);
        if (qc == 0) atomicAdd(&dn[mqw + 8 * rp + qr], v);
    }
    __syncthreads();

    // epilogue: divide, ELU, store (warp: 16q x 64d)
    {
        float i0 = 1.0f / fmaxf(dn[mqw + qr],     1e-30f);
        float i1 = 1.0f / fmaxf(dn[mqw + 8 + qr], 1e-30f);
        int r0 = q0 + mqw + qr;
#pragma unroll
        for (int nb = 0; nb < 8; nb++) {
            int col = dw + 8 * nb + 2 * qc;
            float v0 = oacc[nb][0] * i0, v1 = oacc[nb][1] * i0;
            float v2 = oacc[nb][2] * i1, v3 = oacc[nb][3] * i1;
            v0 = (v0 > 0.f) ? v0 : expm1f(v0);
            v1 = (v1 > 0.f) ? v1 : expm1f(v1);
            v2 = (v2 > 0.f) ? v2 : expm1f(v2);
            v3 = (v3 > 0.f) ? v3 : expm1f(v3);
            *(float2*)&out[((size_t)b * N_ + r0)     * DOUT + col] = make_float2(v0, v1);
            *(float2*)&out[((size_t)b * N_ + r0 + 8) * DOUT + col] = make_float2(v2, v3);
        }
    }
}

// ---------------------------------------------------------------------------
// Launch
// ---------------------------------------------------------------------------
extern "C" void kernel_launch(void* const* d_in, const int* in_sizes, int n_in,
                              void* d_out, int out_size) {
    const float* h       = (const float*)d_in[0];   // [8,2048,256] f32
    // d_in[1] = adj (unused by the reference math)
    const int*   adj_eye = (const int*)d_in[2];     // [8,2048,2048] i32
    const float* W       = (const float*)d_in[3];   // [256,128] f32
    float* out = (float*)d_out;                     // [8,2048,128] f32

    // (2*TM + 2*TN) * HST halves + (128 + 64) floats
    const int smem_bytes = (2 * TM + 2 * TN) * HST * 2 + 192 * 4;   // 105,216 B
    cudaFuncSetAttribute(attn, cudaFuncAttributeMaxDynamicSharedMemorySize, smem_bytes);

    gemmW<<<(B_ * N_) / 128, 256>>>(h, W);
    attn<<<dim3(N_ / TM, B_), 256, smem_bytes>>>(adj_eye, out);
}

// round 11
// speedup vs baseline: 1.4204x; 1.0817x over previous
#include <cuda_runtime.h>
#include <cuda_fp16.h>
#include <math.h>
#include <stdint.h>

#define B_   8
#define N_   2048
#define DIN  256
#define DOUT 128
#define ROWZ 75        // rows [0,75) get attscore = 0
#define TM   64        // queries per block
#define TN   64        // keys per tile (double-buffered)
#define HST  136       // Q/K half-stride (68 words: conflict-free fragments)
#define VST  72        // Vt/P half-stride (36 words: conflict-free fragments)

// Scratch (device globals: allocation-free)
__device__ __half g_Whh[B_ * N_ * DOUT];   // 4 MB   Wh, fp16, row-major [n][d]
__device__ __half g_WhT[B_ * DOUT * N_];   // 4 MB   Wh^T, fp16, [d][n]
__device__ float  g_inv [B_ * N_];         // 64 KB  fp32 inverse row norms

__device__ __forceinline__ float to_tf32(float x) {
    unsigned u; asm("cvt.rna.tf32.f32 %0, %1;" : "=r"(u) : "f"(x));
    return __uint_as_float(u);
}
__device__ __forceinline__ void mma_tf32(float d[4], const unsigned a[4], const unsigned b[2]) {
    asm volatile(
        "mma.sync.aligned.m16n8k8.row.col.f32.tf32.tf32.f32 "
        "{%0,%1,%2,%3}, {%4,%5,%6,%7}, {%8,%9}, {%0,%1,%2,%3};\n"
        : "+f"(d[0]), "+f"(d[1]), "+f"(d[2]), "+f"(d[3])
        : "r"(a[0]), "r"(a[1]), "r"(a[2]), "r"(a[3]), "r"(b[0]), "r"(b[1]));
}
__device__ __forceinline__ void mma_f16(float d[4], const unsigned a[4], const unsigned b[2]) {
    asm volatile(
        "mma.sync.aligned.m16n8k16.row.col.f32.f16.f16.f32 "
        "{%0,%1,%2,%3}, {%4,%5,%6,%7}, {%8,%9}, {%0,%1,%2,%3};\n"
        : "+f"(d[0]), "+f"(d[1]), "+f"(d[2]), "+f"(d[3])
        : "r"(a[0]), "r"(a[1]), "r"(a[2]), "r"(a[3]), "r"(b[0]), "r"(b[1]));
}
__device__ __forceinline__ uint32_t cvta_s(const void* p) {
    uint32_t a; asm("{ .reg .u64 t; cvta.to.shared.u64 t, %1; cvt.u32.u64 %0, t; }"
                    : "=r"(a) : "l"(p));
    return a;
}
#define CP_ASYNC16(s, g) \
    asm volatile("cp.async.cg.shared.global [%0], [%1], 16;" :: "r"(s), "l"(g) : "memory")
#define CP_COMMIT() asm volatile("cp.async.commit_group;" ::: "memory")
#define CP_WAIT0()  asm volatile("cp.async.wait_group 0;"  ::: "memory")

// ---------------------------------------------------------------------------
// Phase 1: Wh = h @ W on tf32 MMA, fused row-norm. Outputs fp16 Wh + Wh^T + inv.
// (unchanged — passing)
// ---------------------------------------------------------------------------
__global__ __launch_bounds__(256) void gemmW(const float* __restrict__ h,
                                             const float* __restrict__ W) {
    __shared__ float hs[128 * 36];
    __shared__ float Ws[32 * 132];
    __shared__ float sq[128];

    const int r0  = blockIdx.x * 128;
    const int tid = threadIdx.x;
    const int w   = tid >> 5, lane = tid & 31;
    const int mqw = (w & 3) * 32, dw = (w >> 2) * 64;
    const int qr  = lane >> 2,  qc = lane & 3;

    if (tid < 128) sq[tid] = 0.0f;

    float acc[2][8][4];
#pragma unroll
    for (int mb = 0; mb < 2; mb++)
#pragma unroll
        for (int nb = 0; nb < 8; nb++)
#pragma unroll
            for (int c = 0; c < 4; c++) acc[mb][nb][c] = 0.0f;

    for (int kc = 0; kc < 8; kc++) {
        __syncthreads();
#pragma unroll
        for (int i = tid; i < 128 * 8; i += 256) {
            int r = i >> 3, g = (i & 7) * 4;
            float4 v = *(const float4*)&h[(size_t)(r0 + r) * DIN + kc * 32 + g];
            v.x = to_tf32(v.x); v.y = to_tf32(v.y); v.z = to_tf32(v.z); v.w = to_tf32(v.w);
            *(float4*)&hs[r * 36 + g] = v;
        }
#pragma unroll
        for (int i = tid; i < 32 * 32; i += 256) {
            int r = i >> 5, g = (i & 31) * 4;
            float4 v = *(const float4*)&W[(size_t)(kc * 32 + r) * DOUT + g];
            v.x = to_tf32(v.x); v.y = to_tf32(v.y); v.z = to_tf32(v.z); v.w = to_tf32(v.w);
            *(float4*)&Ws[r * 132 + g] = v;
        }
        __syncthreads();

#pragma unroll
        for (int k0 = 0; k0 < 32; k0 += 8) {
            unsigned a[2][4];
#pragma unroll
            for (int mb = 0; mb < 2; mb++) {
                int base = (mqw + 16 * mb + qr) * 36 + k0 + qc;
                a[mb][0] = *(const unsigned*)&hs[base];
                a[mb][1] = *(const unsigned*)&hs[base + 8 * 36];
                a[mb][2] = *(const unsigned*)&hs[base + 4];
                a[mb][3] = *(const unsigned*)&hs[base + 8 * 36 + 4];
            }
#pragma unroll
            for (int nb = 0; nb < 8; nb++) {
                unsigned bb[2];
                bb[0] = *(const unsigned*)&Ws[(k0 + qc) * 132 + dw + 8 * nb + qr];
                bb[1] = *(const unsigned*)&Ws[(k0 + 4 + qc) * 132 + dw + 8 * nb + qr];
                mma_tf32(acc[0][nb], a[0], bb);
                mma_tf32(acc[1][nb], a[1], bb);
            }
        }
    }

#pragma unroll
    for (int mb = 0; mb < 2; mb++) {
        float s0 = 0.0f, s1 = 0.0f;
#pragma unroll
        for (int nb = 0; nb < 8; nb++) {
            s0 += acc[mb][nb][0] * acc[mb][nb][0] + acc[mb][nb][1] * acc[mb][nb][1];
            s1 += acc[mb][nb][2] * acc[mb][nb][2] + acc[mb][nb][3] * acc[mb][nb][3];
        }
        s0 += __shfl_xor_sync(0xffffffffu, s0, 1); s0 += __shfl_xor_sync(0xffffffffu, s0, 2);
        s1 += __shfl_xor_sync(0xffffffffu, s1, 1); s1 += __shfl_xor_sync(0xffffffffu, s1, 2);
        if (qc == 0) {
            atomicAdd(&sq[mqw + 16 * mb + qr],     s0);
            atomicAdd(&sq[mqw + 16 * mb + 8 + qr], s1);
        }
    }
    __syncthreads();

    const int bb_  = r0 >> 11;
    const int rl0  = r0 & 2047;
    __half* WT = g_WhT + (size_t)bb_ * DOUT * N_;

#pragma unroll
    for (int mb = 0; mb < 2; mb++)
#pragma unroll
        for (int nb = 0; nb < 8; nb++) {
            int col = dw + 8 * nb + 2 * qc;
            int ra  = mqw + 16 * mb + qr, rb = ra + 8;
            __half2 ha = __floats2half2_rn(acc[mb][nb][0], acc[mb][nb][1]);
            __half2 hb = __floats2half2_rn(acc[mb][nb][2], acc[mb][nb][3]);
            *(__half2*)&g_Whh[(size_t)(r0 + ra) * DOUT + col] = ha;
            *(__half2*)&g_Whh[(size_t)(r0 + rb) * DOUT + col] = hb;
            WT[(size_t)col       * N_ + rl0 + ra] = __low2half(ha);
            WT[(size_t)(col + 1) * N_ + rl0 + ra] = __high2half(ha);
            WT[(size_t)col       * N_ + rl0 + rb] = __low2half(hb);
            WT[(size_t)(col + 1) * N_ + rl0 + rb] = __high2half(hb);
        }
    if (tid < 128) g_inv[r0 + tid] = 1.0f / fmaxf(sqrtf(sq[tid]), 1e-12f);
}

// ---------------------------------------------------------------------------
// Phase 2: fp16 MMA attention, cp.async double-buffered K/Vt pipeline.
// 256 threads, TM=64, TN=64. Warps: 4 bands(16q) x 2 splits (32k S / 64d PV).
// ---------------------------------------------------------------------------
__global__ __launch_bounds__(256, 2) void attn(const int* __restrict__ adj,
                                               float* __restrict__ out) {
    extern __shared__ __align__(16) char smraw[];
    __half* Qh  = (__half*)smraw;                 // [64][136]
    __half* Kb  = Qh + TM * HST;                  // 2 x [64][136]
    __half* Vb  = Kb + 2 * TN * HST;              // 2 x [128][72] (d-major)
    __half* Ps  = Vb + 2 * DOUT * VST;            // [64][72]
    float*  dn  = (float*)(Ps + TM * VST);        // [64]

    const uint32_t sQ = cvta_s(Qh), sK = cvta_s(Kb), sV = cvta_s(Vb);

    const int b     = blockIdx.y;
    const int q0    = blockIdx.x * TM;
    const int tid   = threadIdx.x;
    const int w     = tid >> 5, lane = tid & 31;
    const int band  = w & 3, split = w >> 2;
    const int mqw   = band * 16;
    const int nkw   = split * 32;                 // S key offset
    const int dw    = split * 64;                 // PV d offset
    const int qr    = lane >> 2, qc = lane & 3;

    const __half* WhB  = g_Whh + (size_t)b * N_ * DOUT;
    const __half* WtB  = g_WhT + (size_t)b * DOUT * N_;
    const float*  invB = g_inv + (size_t)b * N_;
    const int*    adjB = adj   + (size_t)b * N_ * N_;

    // prologue group 0: Q tile + K/Vt tile 0
#pragma unroll
    for (int i = tid; i < TM * 16; i += 256) {
        int r = i >> 4, ho = (i & 15) * 8;
        CP_ASYNC16(sQ + (r * HST + ho) * 2, WhB + (size_t)(q0 + r) * DOUT + ho);
        CP_ASYNC16(sK + (r * HST + ho) * 2, WhB + (size_t)r * DOUT + ho);
    }
#pragma unroll
    for (int i = tid; i < DOUT * 8; i += 256) {
        int r = i >> 3, co = (i & 7) * 8;
        CP_ASYNC16(sV + (r * VST + co) * 2, WtB + (size_t)r * N_ + co);
    }
    CP_COMMIT();
    if (tid < TM) dn[tid] = 0.0f;

    float ivq[2]; bool zq[2];
#pragma unroll
    for (int rp = 0; rp < 2; rp++) {
        int row = mqw + 8 * rp + qr;
        ivq[rp] = __ldg(&invB[q0 + row]);
        zq[rp]  = (q0 + row) < ROWZ;
    }
    const int* ap[2];
#pragma unroll
    for (int rp = 0; rp < 2; rp++)
        ap[rp] = adjB + (size_t)(q0 + mqw + 8 * rp + qr) * N_ + nkw + 2 * qc;

    float oacc[8][4];
#pragma unroll
    for (int nb = 0; nb < 8; nb++)
#pragma unroll
        for (int c = 0; c < 4; c++) oacc[nb][c] = 0.0f;
    float rsum[2] = {0.f, 0.f};

    for (int it = 0; it < N_ / TN; it++) {
        const int m0  = it * TN;
        const int cur = it & 1;

        CP_WAIT0();          // my tile-it copies done
        __syncthreads();     // everyone's copies done; prev iter's reads of alt buffer done

        // issue tile it+1 into alternate buffer (hidden under this tile's compute)
        if (it < N_ / TN - 1) {
            const int mn = m0 + TN, alt = cur ^ 1;
#pragma unroll
            for (int i = tid; i < TN * 16; i += 256) {
                int r = i >> 4, ho = (i & 15) * 8;
                CP_ASYNC16(sK + (alt * TN * HST + r * HST + ho) * 2,
                           WhB + (size_t)(mn + r) * DOUT + ho);
            }
#pragma unroll
            for (int i = tid; i < DOUT * 8; i += 256) {
                int r = i >> 3, co = (i & 7) * 8;
                CP_ASYNC16(sV + (alt * DOUT * VST + r * VST + co) * 2,
                           WtB + (size_t)r * N_ + mn + co);
            }
        }
        CP_COMMIT();

        // adj + invk register prefetch (consumed after S — latency shadowed)
        unsigned msk = 0;
#pragma unroll
        for (int rp = 0; rp < 2; rp++) {
#pragma unroll
            for (int nb = 0; nb < 4; nb++) {
                int2 v = *(const int2*)(ap[rp] + 8 * nb);
                msk |= (unsigned)(v.x > 0) << (rp * 8 + nb * 2);
                msk |= (unsigned)(v.y > 0) << (rp * 8 + nb * 2 + 1);
            }
            ap[rp] += TN;
        }
        float2 ivk[4];
#pragma unroll
        for (int nb = 0; nb < 4; nb++)
            ivk[nb] = *(const float2*)&invB[m0 + nkw + 8 * nb + 2 * qc];

        // ---- S = Q.K^T  (warp: 16q x 32k) ----
        const __half* Kc = Kb + cur * TN * HST;
        float sacc[4][4];
#pragma unroll
        for (int nb = 0; nb < 4; nb++)
#pragma unroll
            for (int c = 0; c < 4; c++) sacc[nb][c] = 0.0f;

#pragma unroll
        for (int k0 = 0; k0 < DOUT; k0 += 16) {
            unsigned a[4];
            int base = (mqw + qr) * HST + k0 + 2 * qc;
            a[0] = *(const unsigned*)&Qh[base];
            a[1] = *(const unsigned*)&Qh[base + 8 * HST];
            a[2] = *(const unsigned*)&Qh[base + 8];
            a[3] = *(const unsigned*)&Qh[base + 8 * HST + 8];
#pragma unroll
            for (int nb = 0; nb < 4; nb++) {
                int bbase = (nkw + 8 * nb + qr) * HST + k0 + 2 * qc;
                unsigned bb[2];
                bb[0] = *(const unsigned*)&Kc[bbase];
                bb[1] = *(const unsigned*)&Kc[bbase + 8];
                mma_f16(sacc[nb], a, bb);
            }
        }

        // ---- scale + mask + exp -> P (fp16) ----
#pragma unroll
        for (int nb = 0; nb < 4; nb++) {
            int cb = nkw + 8 * nb + 2 * qc;
            float k0i = ivk[nb].x, k1i = ivk[nb].y;
            unsigned ml = msk >> (nb * 2);
            unsigned mh = msk >> (8 + nb * 2);
            float p0 = (ml & 1u) ? __expf(zq[0] ? 0.f : sacc[nb][0] * ivq[0] * k0i) : 0.f;
            float p1 = (ml & 2u) ? __expf(zq[0] ? 0.f : sacc[nb][1] * ivq[0] * k1i) : 0.f;
            float p2 = (mh & 1u) ? __expf(zq[1] ? 0.f : sacc[nb][2] * ivq[1] * k0i) : 0.f;
            float p3 = (mh & 2u) ? __expf(zq[1] ? 0.f : sacc[nb][3] * ivq[1] * k1i) : 0.f;
            __half2 ha = __floats2half2_rn(p0, p1);
            __half2 hb = __floats2half2_rn(p2, p3);
            float2 fa = __half22float2(ha), fb = __half22float2(hb);
            rsum[0] += fa.x + fa.y;
            rsum[1] += fb.x + fb.y;
            *(__half2*)&Ps[(mqw + qr) * VST + cb]     = ha;
            *(__half2*)&Ps[(mqw + 8 + qr) * VST + cb] = hb;
        }
        __syncthreads();   // P complete (cross-split reads next)

        // ---- O += P.V  (warp: 16q x 64d, B = Vt[d][key]) ----
        const __half* Vc = Vb + cur * DOUT * VST;
#pragma unroll
        for (int k0 = 0; k0 < TN; k0 += 16) {
            unsigned a[4];
            int base = (mqw + qr) * VST + k0 + 2 * qc;
            a[0] = *(const unsigned*)&Ps[base];
            a[1] = *(const unsigned*)&Ps[base + 8 * VST];
            a[2] = *(const unsigned*)&Ps[base + 8];
            a[3] = *(const unsigned*)&Ps[base + 8 * VST + 8];
#pragma unroll
            for (int nb = 0; nb < 8; nb++) {
                int bbase = (dw + 8 * nb + qr) * VST + k0 + 2 * qc;
                unsigned bb[2];
                bb[0] = *(const unsigned*)&Vc[bbase];
                bb[1] = *(const unsigned*)&Vc[bbase + 8];
                mma_f16(oacc[nb], a, bb);
            }
        }
    }

    // denominators (two splits per row add their halves)
#pragma unroll
    for (int rp = 0; rp < 2; rp++) {
        float v = rsum[rp];
        v += __shfl_xor_sync(0xffffffffu, v, 1);
        v += __shfl_xor_sync(0xffffffffu, v, 2);
        if (qc == 0) atomicAdd(&dn[mqw + 8 * rp + qr], v);
    }
    __syncthreads();

    // epilogue: divide, ELU, store (warp: 16q x 64d)
    {
        float i0 = 1.0f / fmaxf(dn[mqw + qr],     1e-30f);
        float i1 = 1.0f / fmaxf(dn[mqw + 8 + qr], 1e-30f);
        int r0 = q0 + mqw + qr;
#pragma unroll
        for (int nb = 0; nb < 8; nb++) {
            int col = dw + 8 * nb + 2 * qc;
            float v0 = oacc[nb][0] * i0, v1 = oacc[nb][1] * i0;
            float v2 = oacc[nb][2] * i1, v3 = oacc[nb][3] * i1;
            v0 = (v0 > 0.f) ? v0 : expm1f(v0);
            v1 = (v1 > 0.f) ? v1 : expm1f(v1);
            v2 = (v2 > 0.f) ? v2 : expm1f(v2);
            v3 = (v3 > 0.f) ? v3 : expm1f(v3);
            *(float2*)&out[((size_t)b * N_ + r0)     * DOUT + col] = make_float2(v0, v1);
            *(float2*)&out[((size_t)b * N_ + r0 + 8) * DOUT + col] = make_float2(v2, v3);
        }
    }
}

// ---------------------------------------------------------------------------
// Launch
// ---------------------------------------------------------------------------
extern "C" void kernel_launch(void* const* d_in, const int* in_sizes, int n_in,
                              void* d_out, int out_size) {
    const float* h       = (const float*)d_in[0];   // [8,2048,256] f32
    // d_in[1] = adj (unused by the reference math)
    const int*   adj_eye = (const int*)d_in[2];     // [8,2048,2048] i32
    const float* W       = (const float*)d_in[3];   // [256,128] f32
    float* out = (float*)d_out;                     // [8,2048,128] f32

    const int smem_bytes =
        (TM * HST + 2 * TN * HST + 2 * DOUT * VST + TM * VST) * 2 + TM * 4;  // 98,560 B
    cudaFuncSetAttribute(attn, cudaFuncAttributeMaxDynamicSharedMemorySize, smem_bytes);

    gemmW<<<(B_ * N_) / 128, 256>>>(h, W);
    attn<<<dim3(N_ / TM, B_), 256, smem_bytes>>>(adj_eye, out);
}